// round 15
// baseline (speedup 1.0000x reference)
#include <cuda_runtime.h>
#include <cuda_fp16.h>
#include <cstdint>
#include <cstddef>

#define BS   4
#define SEQ  1024
#define NH   16
#define HD   64
#define DM   1024
#define ER_L 2047
#define ER_PITCH 2049
#define SCALE_L2 0.18033688011112042f   /* 0.125 * log2(e) */

__device__ __half g_ah[3][BS*SEQ*DM];
__device__ __half g_wh[3][DM*DM];
__device__ __half g_q[BS*NH*SEQ*HD];
__device__ __half g_k[BS*NH*SEQ*HD];
__device__ __half g_v[BS*NH*SEQ*HD];
__device__ __half g_er[NH*ER_PITCH*HD];
__device__ float2 g_stats[BS*NH*SEQ];
__device__ float  g_mrun[(size_t)BS*NH*SEQ*16];
__device__ __half g_lgh[(size_t)BS*NH*SEQ*SEQ];     // exponentiated fp16 logits
__device__ float  g_scratch[(size_t)BS*NH*SEQ*SEQ]; // attn fallback

__device__ __forceinline__ float ex2(float x) {
    float y; asm("ex2.approx.ftz.f32 %0, %1;" : "=f"(y) : "f"(x)); return y;
}
__device__ __forceinline__ uint32_t pack_h2(float a, float b) {
    __half2 h = __floats2half2_rn(a, b);
    return *(uint32_t*)&h;
}
__device__ __forceinline__ uint32_t hmul2u(uint32_t a, uint32_t b) {
    __half2 r = __hmul2(*(__half2*)&a, *(__half2*)&b);
    return *(uint32_t*)&r;
}
__device__ __forceinline__ void mma16(float* c, const uint32_t* a, const uint32_t* b) {
    asm volatile(
        "mma.sync.aligned.m16n8k16.row.col.f32.f16.f16.f32 "
        "{%0,%1,%2,%3},{%4,%5,%6,%7},{%8,%9},{%0,%1,%2,%3};"
        : "+f"(c[0]), "+f"(c[1]), "+f"(c[2]), "+f"(c[3])
        : "r"(a[0]), "r"(a[1]), "r"(a[2]), "r"(a[3]), "r"(b[0]), "r"(b[1]));
}
__device__ __forceinline__ void ldsm4(uint32_t* r, uint32_t a) {
    asm volatile("ldmatrix.sync.aligned.m8n8.x4.shared.b16 {%0,%1,%2,%3}, [%4];"
                 : "=r"(r[0]), "=r"(r[1]), "=r"(r[2]), "=r"(r[3]) : "r"(a));
}
__device__ __forceinline__ void ldsm4t(uint32_t* r, uint32_t a) {
    asm volatile("ldmatrix.sync.aligned.m8n8.x4.trans.shared.b16 {%0,%1,%2,%3}, [%4];"
                 : "=r"(r[0]), "=r"(r[1]), "=r"(r[2]), "=r"(r[3]) : "r"(a));
}
__device__ __forceinline__ void ldsm2(uint32_t* r, uint32_t a) {
    asm volatile("ldmatrix.sync.aligned.m8n8.x2.shared.b16 {%0,%1}, [%2];"
                 : "=r"(r[0]), "=r"(r[1]) : "r"(a));
}
__device__ __forceinline__ uint32_t s2u(const void* p) {
    uint32_t a;
    asm("{ .reg .u64 t; cvta.to.shared.u64 t, %1; cvt.u32.u64 %0, t; }" : "=r"(a) : "l"(p));
    return a;
}
__device__ __forceinline__ void cpa16(uint32_t dst, const void* src, int nbytes) {
    asm volatile("cp.async.cg.shared.global [%0], [%1], 16, %2;"
                 :: "r"(dst), "l"(src), "r"(nbytes));
}
__device__ __forceinline__ void cpa_commit() { asm volatile("cp.async.commit_group;" ::: "memory"); }
__device__ __forceinline__ void cpa_wait0()  { asm volatile("cp.async.wait_group 0;" ::: "memory"); }
__device__ __forceinline__ void cpa_wait1()  { asm volatile("cp.async.wait_group 1;" ::: "memory"); }
__device__ __forceinline__ void cpa_wait2()  { asm volatile("cp.async.wait_group 2;" ::: "memory"); }

// ---------------------------------------------------------------------------
__global__ void cvt_all_kernel(
    const float* __restrict__ q, const float* __restrict__ k, const float* __restrict__ v,
    const float* __restrict__ wq, const float* __restrict__ wk, const float* __restrict__ wv,
    const float* __restrict__ er,
    __half* __restrict__ ah, __half* __restrict__ wh, __half* __restrict__ ger)
{
    size_t qi = (size_t)blockIdx.x * 256 + threadIdx.x;
    const float* src; __half* dst; size_t off;
    if (qi < 3145728) {
        size_t seg = qi >> 20;
        src = (seg == 0) ? q : (seg == 1) ? k : v;
        dst = ah + seg * (size_t)(BS*SEQ*DM);
        off = qi & 1048575;
    } else if (qi < 3932160) {
        size_t r = qi - 3145728, seg = r >> 18;
        src = (seg == 0) ? wq : (seg == 1) ? wk : wv;
        dst = wh + seg * (size_t)(DM*DM);
        off = r & 262143;
    } else {
        src = er; dst = ger; off = qi - 3932160;
    }
    off <<= 2;
    float4 x = *(const float4*)(src + off);
    *(__half2*)(dst + off)     = __floats2half2_rn(x.x, x.y);
    *(__half2*)(dst + off + 2) = __floats2half2_rn(x.z, x.w);
}

// ---------------------------------------------------------------------------
// Projections (fp16 mma), 2-stage cp.async pipeline.
// ---------------------------------------------------------------------------
__global__ void __launch_bounds__(256) proj_kernel(
    const __half* __restrict__ Ab, const __half* __restrict__ Wb,
    const float* __restrict__ b0, const float* __restrict__ b1, const float* __restrict__ b2,
    __half* __restrict__ o0, __half* __restrict__ o1, __half* __restrict__ o2)
{
    const int z = blockIdx.z;
    const __half* A = Ab + (size_t)z * (BS*SEQ*DM);
    const __half* W = Wb + (size_t)z * (DM*DM);
    const float* bias = (z == 0) ? b0 : (z == 1) ? b1 : b2;
    __half* outp      = (z == 0) ? o0 : (z == 1) ? o1 : o2;

    extern __shared__ char psm[];
    const int tid  = threadIdx.x;
    const int warp = tid >> 5, lane = tid & 31;
    const int g = lane >> 2, t = lane & 3;
    const int wm = warp >> 2, wn = warp & 3;
    const int m_blk = blockIdx.y * 128;
    const int n_blk = blockIdx.x * 128;

    const int ar   = (lane & 7) + ((lane >> 3) & 1) * 8;
    const int acol = (lane >> 4) * 8;
    const int br   = lane & 7;
    const int bg   = ((lane & 15) >> 3) * 8;

    float acc[4][4][4];
#pragma unroll
    for (int mi = 0; mi < 4; mi++)
#pragma unroll
        for (int ni = 0; ni < 4; ni++)
#pragma unroll
            for (int x = 0; x < 4; x++) acc[mi][ni][x] = 0.f;

    const uint32_t s_u = s2u(psm);

#define P_ISSUE(ci) do {                                                      \
        uint32_t su_ = s_u + (((ci) & 1) ? 36864u : 0u);                      \
        int kc_ = (ci) * 64;                                                  \
        for (int i = tid; i < 128 * 8; i += 256) {                            \
            int r_ = i >> 3, c_ = (i & 7) << 3;                               \
            cpa16(su_ + (r_ * 72 + c_) * 2, A + (size_t)(m_blk + r_) * DM + kc_ + c_, 16); \
            cpa16(su_ + 18432 + (r_ * 72 + c_) * 2, W + (size_t)(n_blk + r_) * DM + kc_ + c_, 16); \
        }                                                                     \
        cpa_commit();                                                         \
    } while (0)

    P_ISSUE(0);
    for (int ci = 0; ci < 16; ci++) {
        if (ci < 15) { P_ISSUE(ci + 1); cpa_wait1(); }
        else         { cpa_wait0(); }
        __syncthreads();
        const uint32_t a_u = s_u + ((ci & 1) ? 36864u : 0u);
        const uint32_t w_u = a_u + 18432u;
#pragma unroll
        for (int ks = 0; ks < 4; ks++) {
            const int kk = ks * 16;
            uint32_t af[4][4];
#pragma unroll
            for (int mi = 0; mi < 4; mi++)
                ldsm4(af[mi], a_u + ((wm * 64 + mi * 16 + ar) * 72 + kk + acol) * 2);
#pragma unroll
            for (int ni = 0; ni < 4; ni++) {
                uint32_t bf[2];
                ldsm2(bf, w_u + ((wn * 32 + ni * 8 + br) * 72 + kk + bg) * 2);
#pragma unroll
                for (int mi = 0; mi < 4; mi++)
                    mma16(acc[mi][ni], af[mi], bf);
            }
        }
        __syncthreads();
    }
#undef P_ISSUE

#pragma unroll
    for (int mi = 0; mi < 4; mi++) {
        int row0 = m_blk + wm * 64 + mi * 16 + g;
        int row1 = row0 + 8;
#pragma unroll
        for (int ni = 0; ni < 4; ni++) {
            int col = n_blk + wn * 32 + ni * 8 + 2 * t;
            float bb0 = bias[col], bb1 = bias[col + 1];
            int h_i = col >> 6, d_i = col & 63;
            {
                int b_i = row0 >> 10, s_i = row0 & 1023;
                size_t addr = ((size_t)(b_i * NH + h_i) * SEQ + s_i) * HD + d_i;
                *(__half2*)(outp + addr) = __floats2half2_rn(acc[mi][ni][0] + bb0, acc[mi][ni][1] + bb1);
            }
            {
                int b_i = row1 >> 10, s_i = row1 & 1023;
                size_t addr = ((size_t)(b_i * NH + h_i) * SEQ + s_i) * HD + d_i;
                *(__half2*)(outp + addr) = __floats2half2_rn(acc[mi][ni][2] + bb0, acc[mi][ni][3] + bb1);
            }
        }
    }
}

// ---------------------------------------------------------------------------
// Pass 1: scores + rolling Er band (fp16 R) + online stats.
// Stores p' = ex2(sc - m_run_tile) as fp16 to g_lgh + m_run per (row,tile).
// smem 45056 B -> 5 blk/SM. K double-buffered.
// ---------------------------------------------------------------------------
__global__ void __launch_bounds__(128, 5) attn1_kernel(
    const __half* __restrict__ gq, const __half* __restrict__ gk,
    const __half* __restrict__ ger,
    __half* __restrict__ lgh_o, float* __restrict__ mrun_o,
    float2* __restrict__ stats)
{
    extern __shared__ char smem_c[];
    __half* k_s0 = (__half*)smem_c;              // [64][72]
    __half* k_s1 = (__half*)(smem_c + 9216);     // [64][72]
    __half* er_s = (__half*)(smem_c + 18432);    // [64][72]
    __half* R_s  = (__half*)(smem_c + 27648);    // [64][136] circular band

    const int tid  = threadIdx.x;
    const int warp = tid >> 5, lane = tid & 31;
    const int g = lane >> 2, t = lane & 3;
    const int rs = warp << 4;
    const int s0 = blockIdx.x << 6;
    const int bh = blockIdx.y;
    const int h  = bh & 15;

    const __half* qp  = gq + ((size_t)bh * SEQ + s0) * HD;
    const __half* kp  = gk + (size_t)bh * SEQ * HD;
    const __half* erp = ger + (size_t)h * ER_PITCH * HD;
    __half* lgh_p = lgh_o + ((size_t)bh * SEQ + s0) * SEQ;
    float* mrun_p = mrun_o + ((size_t)bh * SEQ + s0) * 16;

    const uint32_t k0_u = s2u(k_s0);
    const uint32_t k1_u = s2u(k_s1);
    const uint32_t er_u = s2u(er_s);
    const int base_abs = 960 - s0;
    const int sA = rs + g, sB = rs + g + 8;

    const int ar   = (lane & 7) + ((lane >> 3) & 1) * 8;
    const int acol = (lane >> 4) * 8;
    const int l8   = lane & 7;
    const int bg8  = (lane >> 3) * 8;

#define LOAD_TILE(dstu, srcp) do {                                            \
        for (int i = tid; i < 512; i += 128) {                                \
            int r_ = i >> 3, c_ = (i & 7) << 3;                               \
            cpa16((dstu) + (r_ * 72 + c_) * 2, (srcp) + (size_t)r_ * HD + c_, 16); \
        }                                                                     \
        cpa_commit();                                                         \
    } while (0)

#define ISSUE_ER(bi) do {                                                     \
        int es_ = (bi) << 6;                                                  \
        for (int i = tid; i < 512; i += 128) {                                \
            int r_ = i >> 3, c_ = (i & 7) << 3;                               \
            int ar_ = base_abs + es_ + r_;                                    \
            cpa16(er_u + (r_ * 72 + c_) * 2, erp + (size_t)ar_ * HD + c_,     \
                  (ar_ < ER_L) ? 16 : 0);                                     \
        }                                                                     \
        cpa_commit();                                                         \
    } while (0)

#define R_MMA(bi) do {                                                        \
        int es_ = (bi) << 6;                                                  \
        _Pragma("unroll")                                                     \
        for (int nf = 0; nf < 8; nf++) {                                      \
            uint32_t bb[8];                                                   \
            ldsm4(bb,     er_u + ((nf * 8 + l8) * 72 + bg8) * 2);             \
            ldsm4(bb + 4, er_u + ((nf * 8 + l8) * 72 + 32 + bg8) * 2);        \
            float c4[4] = {0.f, 0.f, 0.f, 0.f};                               \
            mma16(c4, qa[0], bb);                                             \
            mma16(c4, qa[1], bb + 2);                                         \
            mma16(c4, qa[2], bb + 4);                                         \
            mma16(c4, qa[3], bb + 6);                                         \
            int j0 = (es_ + nf * 8 + 2 * t) & 127;                            \
            *(uint32_t*)&R_s[sA * 136 + j0] = pack_h2(c4[0], c4[1]);          \
            *(uint32_t*)&R_s[sB * 136 + j0] = pack_h2(c4[2], c4[3]);          \
        }                                                                     \
    } while (0)

    // q tile -> A fragments (staged via er_s)
    LOAD_TILE(er_u, qp);
    cpa_wait0();
    __syncthreads();
    uint32_t qa[4][4];
#pragma unroll
    for (int ks = 0; ks < 4; ks++)
        ldsm4(qa[ks], er_u + ((rs + ar) * 72 + ks * 16 + acol) * 2);
    __syncthreads();

    ISSUE_ER(0);
    cpa_wait0();
    __syncthreads();
    R_MMA(0);
    __syncthreads();
    ISSUE_ER(1);          // pending: ER1
    LOAD_TILE(k0_u, kp);  // pending: ER1, K0

    float m0 = -1e30f, m1 = -1e30f, sum0 = 0.f, sum1 = 0.f;

    for (int tt = 0; tt < 16; tt++) {
        const int t0 = tt << 6;
        const uint32_t kb_u = (tt & 1) ? k1_u : k0_u;

        cpa_wait1();      // ER(tt+1) landed
        __syncthreads();
        R_MMA(tt + 1);
        __syncthreads();
        if (tt < 15) {
            ISSUE_ER(tt + 2);
            LOAD_TILE((tt & 1) ? k0_u : k1_u, kp + (size_t)(t0 + 64) * HD);
            cpa_wait2();  // K(tt) landed
        } else {
            cpa_wait0();
        }
        __syncthreads();

        // scores
        float sc[8][4];
#pragma unroll
        for (int nf = 0; nf < 8; nf++) {
            uint32_t bb[8];
            ldsm4(bb,     kb_u + ((nf * 8 + l8) * 72 + bg8) * 2);
            ldsm4(bb + 4, kb_u + ((nf * 8 + l8) * 72 + 32 + bg8) * 2);
            float c4[4] = {0.f, 0.f, 0.f, 0.f};
            mma16(c4, qa[0], bb);
            mma16(c4, qa[1], bb + 2);
            mma16(c4, qa[2], bb + 4);
            mma16(c4, qa[3], bb + 6);
            int tp = nf * 8 + 2 * t;
            int cb = t0 + 63 + tp;
            sc[nf][0] = (c4[0] + __half2float(R_s[sA * 136 + ((cb     - sA) & 127)])) * SCALE_L2;
            sc[nf][1] = (c4[1] + __half2float(R_s[sA * 136 + ((cb + 1 - sA) & 127)])) * SCALE_L2;
            sc[nf][2] = (c4[2] + __half2float(R_s[sB * 136 + ((cb     - sB) & 127)])) * SCALE_L2;
            sc[nf][3] = (c4[3] + __half2float(R_s[sB * 136 + ((cb + 1 - sB) & 127)])) * SCALE_L2;
        }

        // tile max (quad reduce) -> running max
        float tm0 = -1e30f, tm1 = -1e30f;
#pragma unroll
        for (int nf = 0; nf < 8; nf++) {
            tm0 = fmaxf(tm0, fmaxf(sc[nf][0], sc[nf][1]));
            tm1 = fmaxf(tm1, fmaxf(sc[nf][2], sc[nf][3]));
        }
        tm0 = fmaxf(tm0, __shfl_xor_sync(0xffffffffu, tm0, 1));
        tm0 = fmaxf(tm0, __shfl_xor_sync(0xffffffffu, tm0, 2));
        tm1 = fmaxf(tm1, __shfl_xor_sync(0xffffffffu, tm1, 1));
        tm1 = fmaxf(tm1, __shfl_xor_sync(0xffffffffu, tm1, 2));
        float nm0 = fmaxf(m0, tm0), nm1 = fmaxf(m1, tm1);

        // p' = ex2(sc - nm), store fp16, accumulate sums
        float ts0 = 0.f, ts1 = 0.f;
#pragma unroll
        for (int nf = 0; nf < 8; nf++) {
            float p0 = ex2(sc[nf][0] - nm0), p1 = ex2(sc[nf][1] - nm0);
            float p2 = ex2(sc[nf][2] - nm1), p3 = ex2(sc[nf][3] - nm1);
            ts0 += p0 + p1;  ts1 += p2 + p3;
            int tp = nf * 8 + 2 * t;
            *(uint32_t*)&lgh_p[(size_t)sA * SEQ + t0 + tp] = pack_h2(p0, p1);
            *(uint32_t*)&lgh_p[(size_t)sB * SEQ + t0 + tp] = pack_h2(p2, p3);
        }
        ts0 += __shfl_xor_sync(0xffffffffu, ts0, 1);
        ts0 += __shfl_xor_sync(0xffffffffu, ts0, 2);
        ts1 += __shfl_xor_sync(0xffffffffu, ts1, 1);
        ts1 += __shfl_xor_sync(0xffffffffu, ts1, 2);
        sum0 = sum0 * ex2(m0 - nm0) + ts0;
        sum1 = sum1 * ex2(m1 - nm1) + ts1;
        m0 = nm0; m1 = nm1;
        if (t == 0) {
            mrun_p[(size_t)sA * 16 + tt] = nm0;
            mrun_p[(size_t)sB * 16 + tt] = nm1;
        }
    }

    if (t == 0) {
        stats[(size_t)bh * SEQ + s0 + sA] = make_float2(m0, 1.f / sum0);
        stats[(size_t)bh * SEQ + s0 + sB] = make_float2(m1, 1.f / sum1);
    }
#undef LOAD_TILE
#undef ISSUE_ER
#undef R_MMA
}

// ---------------------------------------------------------------------------
// Pass 2: p' and V both via double-buffered cp.async. P fragments ldsm'd from
// the p' tile and scaled in-register by cf (fp16); normalized attn streamed
// from the same smem tile with coalesced fp32 stores.
// smem: v0|v1|p0|p1 (9216 each) + cf (4096) + st (512) = 41472 B -> 5 blk/SM.
// ---------------------------------------------------------------------------
__global__ void __launch_bounds__(128, 5) attn2_kernel(
    const __half* __restrict__ gv,
    float* __restrict__ out_f, float* __restrict__ attn_o,
    const __half* __restrict__ lgh_o, const float* __restrict__ mrun_o,
    const float2* __restrict__ stats)
{
    extern __shared__ char smem_c[];
    float*  cf_s = (float*)(smem_c + 36864);     // [64][16]
    float2* st_s = (float2*)(smem_c + 40960);    // [64]

    const int tid  = threadIdx.x;
    const int warp = tid >> 5, lane = tid & 31;
    const int g = lane >> 2, t = lane & 3;
    const int rs = warp << 4;
    const int s0 = blockIdx.x << 6;
    const int bh = blockIdx.y;
    const int h  = bh & 15;

    const __half* vp = gv + (size_t)bh * SEQ * HD;
    float* attn_p = attn_o + ((size_t)bh * SEQ + s0) * SEQ;
    const __half* lgh_p = lgh_o + ((size_t)bh * SEQ + s0) * SEQ;

    const uint32_t base_u = s2u(smem_c);
    const uint32_t v_u[2] = { base_u, base_u + 9216u };
    const uint32_t p_u[2] = { base_u + 18432u, base_u + 27648u };
    const int sA = rs + g, sB = rs + g + 8;

    const int ar   = (lane & 7) + ((lane >> 3) & 1) * 8;
    const int acol = (lane >> 4) * 8;
    const int l8   = lane & 7;
    const int bg8  = (lane >> 3) * 8;

    // G(ti) = { p'(ti), V(ti) } into buffer ti&1, one commit group
#define ISSUE_G(ti) do {                                                      \
        int t0_ = (ti) << 6;                                                  \
        uint32_t vu_ = v_u[(ti) & 1], pu_ = p_u[(ti) & 1];                    \
        for (int i = tid; i < 512; i += 128) {                                \
            int r_ = i >> 3, c_ = (i & 7) << 3;                               \
            cpa16(vu_ + (r_ * 72 + c_) * 2, vp + (size_t)(t0_ + r_) * HD + c_, 16); \
            cpa16(pu_ + (r_ * 72 + c_) * 2, lgh_p + (size_t)r_ * SEQ + t0_ + c_, 16); \
        }                                                                     \
        cpa_commit();                                                         \
    } while (0)

    // load stats + raw mrun -> cf = ex2(mrun - m_f) * inv
    if (tid < 64) st_s[tid] = stats[(size_t)bh * SEQ + s0 + tid];
    {
        const float* mrun_p = mrun_o + ((size_t)bh * SEQ + s0) * 16;
#pragma unroll
        for (int i = tid; i < 1024; i += 128) cf_s[i] = mrun_p[i];
    }
    ISSUE_G(0);
    ISSUE_G(1);
    __syncthreads();
#pragma unroll
    for (int i = tid; i < 1024; i += 128) {
        float2 st = st_s[i >> 4];
        cf_s[i] = ex2(cf_s[i] - st.x) * st.y;
    }
    __syncthreads();   // cf_s visible

    float oacc[8][4];
#pragma unroll
    for (int ni = 0; ni < 8; ni++)
#pragma unroll
        for (int x = 0; x < 4; x++) oacc[ni][x] = 0.f;

    // attn-write coords: row per thread pair, 32-col half each
    const int wr = tid >> 1;
    const int wc = (tid & 1) << 5;

    for (int tt = 0; tt < 16; tt++) {
        const int t0 = tt << 6;
        const uint32_t vb_u = v_u[tt & 1];
        const uint32_t pb_u = p_u[tt & 1];

        if (tt < 15) cpa_wait1(); else cpa_wait0();   // G(tt) landed
        __syncthreads();

        // P fragments from p' tile, scaled by cf (fp16)
        float cfA = cf_s[sA * 16 + tt], cfB = cf_s[sB * 16 + tt];
        uint32_t hA = pack_h2(cfA, cfA), hB = pack_h2(cfB, cfB);
        uint32_t pa[4][4];
#pragma unroll
        for (int ks = 0; ks < 4; ks++) {
            ldsm4(pa[ks], pb_u + ((rs + ar) * 72 + ks * 16 + acol) * 2);
            pa[ks][0] = hmul2u(pa[ks][0], hA);
            pa[ks][1] = hmul2u(pa[ks][1], hB);
            pa[ks][2] = hmul2u(pa[ks][2], hA);
            pa[ks][3] = hmul2u(pa[ks][3], hB);
        }
#pragma unroll
        for (int ni = 0; ni < 8; ni++) {
            uint32_t bb[8];
            ldsm4t(bb,     vb_u + ((bg8 + l8) * 72 + ni * 8) * 2);
            ldsm4t(bb + 4, vb_u + ((32 + bg8 + l8) * 72 + ni * 8) * 2);
            mma16(oacc[ni], pa[0], bb);
            mma16(oacc[ni], pa[1], bb + 2);
            mma16(oacc[ni], pa[2], bb + 4);
            mma16(oacc[ni], pa[3], bb + 6);
        }

        // stream normalized attn from the p' tile (coalesced fp32 stores)
        {
            const __half* prow = (const __half*)(smem_c + 18432 + (tt & 1) * 9216) + wr * 72 + wc;
            float cf = cf_s[wr * 16 + tt];
            float* arow = attn_p + (size_t)wr * SEQ + t0 + wc;
#pragma unroll
            for (int j = 0; j < 4; j++) {
                uint4 raw = *(const uint4*)(prow + j * 8);
                __half2* hp = (__half2*)&raw;
                float2 f0 = __half22float2(hp[0]);
                float2 f1 = __half22float2(hp[1]);
                float2 f2 = __half22float2(hp[2]);
                float2 f3 = __half22float2(hp[3]);
                *(float4*)(arow + j * 8)     = make_float4(f0.x * cf, f0.y * cf, f1.x * cf, f1.y * cf);
                *(float4*)(arow + j * 8 + 4) = make_float4(f2.x * cf, f2.y * cf, f3.x * cf, f3.y * cf);
            }
        }
        __syncthreads();   // tile consumed; buffers reusable
        if (tt < 14) ISSUE_G(tt + 2);
    }

    const int b_i = bh >> 4;
    const int gsA = s0 + sA, gsB = s0 + sB;
#pragma unroll
    for (int ni = 0; ni < 8; ni++) {
        int col = h * HD + ni * 8 + 2 * t;
        *(float2*)(out_f + ((size_t)b_i * SEQ + gsA) * DM + col) = make_float2(oacc[ni][0], oacc[ni][1]);
        *(float2*)(out_f + ((size_t)b_i * SEQ + gsB) * DM + col) = make_float2(oacc[ni][2], oacc[ni][3]);
    }
#undef ISSUE_G
}

// ---------------------------------------------------------------------------
extern "C" void kernel_launch(void* const* d_in, const int* in_sizes, int n_in,
                              void* d_out, int out_size)
{
    const float* query = (const float*)d_in[0];
    const float* key   = (const float*)d_in[1];
    const float* value = (const float*)d_in[2];
    const float* Wq = (const float*)d_in[3];
    const float* bq = (const float*)d_in[4];
    const float* Wk = (const float*)d_in[5];
    const float* bk = (const float*)d_in[6];
    const float* Wv = (const float*)d_in[7];
    const float* bv = (const float*)d_in[8];
    const float* Er = (const float*)d_in[9];
    float* outp = (float*)d_out;

    __half *ah, *wh, *gq, *gk, *gv, *ger, *glgh;
    float *gs, *gmr; float2 *gst;
    cudaGetSymbolAddress((void**)&ah,   g_ah);
    cudaGetSymbolAddress((void**)&wh,   g_wh);
    cudaGetSymbolAddress((void**)&gq,   g_q);
    cudaGetSymbolAddress((void**)&gk,   g_k);
    cudaGetSymbolAddress((void**)&gv,   g_v);
    cudaGetSymbolAddress((void**)&ger,  g_er);
    cudaGetSymbolAddress((void**)&glgh, g_lgh);
    cudaGetSymbolAddress((void**)&gmr,  g_mrun);
    cudaGetSymbolAddress((void**)&gs,   g_scratch);
    cudaGetSymbolAddress((void**)&gst,  g_stats);

    float* attn = (out_size > BS * SEQ * DM) ? (outp + (size_t)BS * SEQ * DM) : gs;

    cvt_all_kernel<<<17409, 256>>>(query, key, value, Wq, Wk, Wv, Er, ah, wh, ger);

    cudaFuncSetAttribute(proj_kernel, cudaFuncAttributeMaxDynamicSharedMemorySize, 73728);
    dim3 gp(DM / 128, (BS * SEQ) / 128, 3);
    proj_kernel<<<gp, 256, 73728>>>(ah, wh, bq, bk, bv, gq, gk, gv);

    cudaFuncSetAttribute(attn1_kernel, cudaFuncAttributeMaxDynamicSharedMemorySize, 45056);
    attn1_kernel<<<dim3(SEQ / 64, BS * NH), 128, 45056>>>(gq, gk, ger, glgh, gmr, gst);

    cudaFuncSetAttribute(attn2_kernel, cudaFuncAttributeMaxDynamicSharedMemorySize, 41472);
    attn2_kernel<<<dim3(SEQ / 64, BS * NH), 128, 41472>>>(gv, outp, attn, glgh, gmr, gst);
}

// round 16
// speedup vs baseline: 1.3421x; 1.3421x over previous
#include <cuda_runtime.h>
#include <cuda_fp16.h>
#include <cstdint>
#include <cstddef>

#define BS   4
#define SEQ  1024
#define NH   16
#define HD   64
#define DM   1024
#define ER_L 2047
#define ER_PITCH 2049
#define SCALE_L2 0.18033688011112042f   /* 0.125 * log2(e) */

__device__ __half g_ah[3][BS*SEQ*DM];
__device__ __half g_wh[3][DM*DM];
__device__ __half g_q[BS*NH*SEQ*HD];
__device__ __half g_k[BS*NH*SEQ*HD];
__device__ __half g_v[BS*NH*SEQ*HD];
__device__ __half g_er[NH*ER_PITCH*HD];
__device__ float2 g_stats[BS*NH*SEQ];
__device__ float  g_mrun[(size_t)BS*NH*SEQ*16];
__device__ __half g_lgh[(size_t)BS*NH*SEQ*SEQ];     // exponentiated fp16 logits
__device__ float  g_scratch[(size_t)BS*NH*SEQ*SEQ]; // attn fallback

__device__ __forceinline__ float ex2(float x) {
    float y; asm("ex2.approx.ftz.f32 %0, %1;" : "=f"(y) : "f"(x)); return y;
}
__device__ __forceinline__ uint32_t pack_h2(float a, float b) {
    __half2 h = __floats2half2_rn(a, b);
    return *(uint32_t*)&h;
}
__device__ __forceinline__ void mma16(float* c, const uint32_t* a, const uint32_t* b) {
    asm volatile(
        "mma.sync.aligned.m16n8k16.row.col.f32.f16.f16.f32 "
        "{%0,%1,%2,%3},{%4,%5,%6,%7},{%8,%9},{%0,%1,%2,%3};"
        : "+f"(c[0]), "+f"(c[1]), "+f"(c[2]), "+f"(c[3])
        : "r"(a[0]), "r"(a[1]), "r"(a[2]), "r"(a[3]), "r"(b[0]), "r"(b[1]));
}
__device__ __forceinline__ void ldsm4(uint32_t* r, uint32_t a) {
    asm volatile("ldmatrix.sync.aligned.m8n8.x4.shared.b16 {%0,%1,%2,%3}, [%4];"
                 : "=r"(r[0]), "=r"(r[1]), "=r"(r[2]), "=r"(r[3]) : "r"(a));
}
__device__ __forceinline__ void ldsm4t(uint32_t* r, uint32_t a) {
    asm volatile("ldmatrix.sync.aligned.m8n8.x4.trans.shared.b16 {%0,%1,%2,%3}, [%4];"
                 : "=r"(r[0]), "=r"(r[1]), "=r"(r[2]), "=r"(r[3]) : "r"(a));
}
__device__ __forceinline__ void ldsm2(uint32_t* r, uint32_t a) {
    asm volatile("ldmatrix.sync.aligned.m8n8.x2.shared.b16 {%0,%1}, [%2];"
                 : "=r"(r[0]), "=r"(r[1]) : "r"(a));
}
__device__ __forceinline__ uint32_t s2u(const void* p) {
    uint32_t a;
    asm("{ .reg .u64 t; cvta.to.shared.u64 t, %1; cvt.u32.u64 %0, t; }" : "=r"(a) : "l"(p));
    return a;
}
__device__ __forceinline__ void cpa16(uint32_t dst, const void* src, int nbytes) {
    asm volatile("cp.async.ca.shared.global [%0], [%1], 16, %2;"
                 :: "r"(dst), "l"(src), "r"(nbytes));
}
__device__ __forceinline__ void cpa_commit() { asm volatile("cp.async.commit_group;" ::: "memory"); }
__device__ __forceinline__ void cpa_wait0()  { asm volatile("cp.async.wait_group 0;" ::: "memory"); }
__device__ __forceinline__ void cpa_wait1()  { asm volatile("cp.async.wait_group 1;" ::: "memory"); }
__device__ __forceinline__ void cpa_wait2()  { asm volatile("cp.async.wait_group 2;" ::: "memory"); }

// ---------------------------------------------------------------------------
__global__ void cvt_all_kernel(
    const float* __restrict__ q, const float* __restrict__ k, const float* __restrict__ v,
    const float* __restrict__ wq, const float* __restrict__ wk, const float* __restrict__ wv,
    const float* __restrict__ er,
    __half* __restrict__ ah, __half* __restrict__ wh, __half* __restrict__ ger)
{
    size_t qi = (size_t)blockIdx.x * 256 + threadIdx.x;
    const float* src; __half* dst; size_t off;
    if (qi < 3145728) {
        size_t seg = qi >> 20;
        src = (seg == 0) ? q : (seg == 1) ? k : v;
        dst = ah + seg * (size_t)(BS*SEQ*DM);
        off = qi & 1048575;
    } else if (qi < 3932160) {
        size_t r = qi - 3145728, seg = r >> 18;
        src = (seg == 0) ? wq : (seg == 1) ? wk : wv;
        dst = wh + seg * (size_t)(DM*DM);
        off = r & 262143;
    } else {
        src = er; dst = ger; off = qi - 3932160;
    }
    off <<= 2;
    float4 x = *(const float4*)(src + off);
    *(__half2*)(dst + off)     = __floats2half2_rn(x.x, x.y);
    *(__half2*)(dst + off + 2) = __floats2half2_rn(x.z, x.w);
}

// ---------------------------------------------------------------------------
// Projections (fp16 mma), 2-stage cp.async pipeline.
// ---------------------------------------------------------------------------
__global__ void __launch_bounds__(256) proj_kernel(
    const __half* __restrict__ Ab, const __half* __restrict__ Wb,
    const float* __restrict__ b0, const float* __restrict__ b1, const float* __restrict__ b2,
    __half* __restrict__ o0, __half* __restrict__ o1, __half* __restrict__ o2)
{
    const int z = blockIdx.z;
    const __half* A = Ab + (size_t)z * (BS*SEQ*DM);
    const __half* W = Wb + (size_t)z * (DM*DM);
    const float* bias = (z == 0) ? b0 : (z == 1) ? b1 : b2;
    __half* outp      = (z == 0) ? o0 : (z == 1) ? o1 : o2;

    extern __shared__ char psm[];
    const int tid  = threadIdx.x;
    const int warp = tid >> 5, lane = tid & 31;
    const int g = lane >> 2, t = lane & 3;
    const int wm = warp >> 2, wn = warp & 3;
    const int m_blk = blockIdx.y * 128;
    const int n_blk = blockIdx.x * 128;

    const int ar   = (lane & 7) + ((lane >> 3) & 1) * 8;
    const int acol = (lane >> 4) * 8;
    const int br   = lane & 7;
    const int bg   = ((lane & 15) >> 3) * 8;

    float acc[4][4][4];
#pragma unroll
    for (int mi = 0; mi < 4; mi++)
#pragma unroll
        for (int ni = 0; ni < 4; ni++)
#pragma unroll
            for (int x = 0; x < 4; x++) acc[mi][ni][x] = 0.f;

    const uint32_t s_u = s2u(psm);

#define P_ISSUE(ci) do {                                                      \
        uint32_t su_ = s_u + (((ci) & 1) ? 36864u : 0u);                      \
        int kc_ = (ci) * 64;                                                  \
        for (int i = tid; i < 128 * 8; i += 256) {                            \
            int r_ = i >> 3, c_ = (i & 7) << 3;                               \
            cpa16(su_ + (r_ * 72 + c_) * 2, A + (size_t)(m_blk + r_) * DM + kc_ + c_, 16); \
            cpa16(su_ + 18432 + (r_ * 72 + c_) * 2, W + (size_t)(n_blk + r_) * DM + kc_ + c_, 16); \
        }                                                                     \
        cpa_commit();                                                         \
    } while (0)

    P_ISSUE(0);
    for (int ci = 0; ci < 16; ci++) {
        if (ci < 15) { P_ISSUE(ci + 1); cpa_wait1(); }
        else         { cpa_wait0(); }
        __syncthreads();
        const uint32_t a_u = s_u + ((ci & 1) ? 36864u : 0u);
        const uint32_t w_u = a_u + 18432u;
#pragma unroll
        for (int ks = 0; ks < 4; ks++) {
            const int kk = ks * 16;
            uint32_t af[4][4];
#pragma unroll
            for (int mi = 0; mi < 4; mi++)
                ldsm4(af[mi], a_u + ((wm * 64 + mi * 16 + ar) * 72 + kk + acol) * 2);
#pragma unroll
            for (int ni = 0; ni < 4; ni++) {
                uint32_t bf[2];
                ldsm2(bf, w_u + ((wn * 32 + ni * 8 + br) * 72 + kk + bg) * 2);
#pragma unroll
                for (int mi = 0; mi < 4; mi++)
                    mma16(acc[mi][ni], af[mi], bf);
            }
        }
        __syncthreads();
    }
#undef P_ISSUE

#pragma unroll
    for (int mi = 0; mi < 4; mi++) {
        int row0 = m_blk + wm * 64 + mi * 16 + g;
        int row1 = row0 + 8;
#pragma unroll
        for (int ni = 0; ni < 4; ni++) {
            int col = n_blk + wn * 32 + ni * 8 + 2 * t;
            float bb0 = bias[col], bb1 = bias[col + 1];
            int h_i = col >> 6, d_i = col & 63;
            {
                int b_i = row0 >> 10, s_i = row0 & 1023;
                size_t addr = ((size_t)(b_i * NH + h_i) * SEQ + s_i) * HD + d_i;
                *(__half2*)(outp + addr) = __floats2half2_rn(acc[mi][ni][0] + bb0, acc[mi][ni][1] + bb1);
            }
            {
                int b_i = row1 >> 10, s_i = row1 & 1023;
                size_t addr = ((size_t)(b_i * NH + h_i) * SEQ + s_i) * HD + d_i;
                *(__half2*)(outp + addr) = __floats2half2_rn(acc[mi][ni][2] + bb0, acc[mi][ni][3] + bb1);
            }
        }
    }
}

// ---------------------------------------------------------------------------
// Pass 1: scores + rolling Er band (fp16 R) + online stats.
// Stores p' = ex2(sc - m_run_tile) as fp16 to g_lgh + m_run per (row,tile).
// mma chains split into two partial accumulators (halved RAW depth).
// smem 45056 B -> 5 blk/SM. K double-buffered.
// ---------------------------------------------------------------------------
__global__ void __launch_bounds__(128, 5) attn1_kernel(
    const __half* __restrict__ gq, const __half* __restrict__ gk,
    const __half* __restrict__ ger,
    __half* __restrict__ lgh_o, float* __restrict__ mrun_o,
    float2* __restrict__ stats)
{
    extern __shared__ char smem_c[];
    __half* k_s0 = (__half*)smem_c;              // [64][72]
    __half* k_s1 = (__half*)(smem_c + 9216);     // [64][72]
    __half* er_s = (__half*)(smem_c + 18432);    // [64][72]
    __half* R_s  = (__half*)(smem_c + 27648);    // [64][136] circular band

    const int tid  = threadIdx.x;
    const int warp = tid >> 5, lane = tid & 31;
    const int g = lane >> 2, t = lane & 3;
    const int rs = warp << 4;
    const int s0 = blockIdx.x << 6;
    const int bh = blockIdx.y;
    const int h  = bh & 15;

    const __half* qp  = gq + ((size_t)bh * SEQ + s0) * HD;
    const __half* kp  = gk + (size_t)bh * SEQ * HD;
    const __half* erp = ger + (size_t)h * ER_PITCH * HD;
    __half* lgh_p = lgh_o + ((size_t)bh * SEQ + s0) * SEQ;
    float* mrun_p = mrun_o + ((size_t)bh * SEQ + s0) * 16;

    const uint32_t k0_u = s2u(k_s0);
    const uint32_t k1_u = s2u(k_s1);
    const uint32_t er_u = s2u(er_s);
    const int base_abs = 960 - s0;
    const int sA = rs + g, sB = rs + g + 8;

    const int ar   = (lane & 7) + ((lane >> 3) & 1) * 8;
    const int acol = (lane >> 4) * 8;
    const int l8   = lane & 7;
    const int bg8  = (lane >> 3) * 8;

#define LOAD_TILE(dstu, srcp) do {                                            \
        for (int i = tid; i < 512; i += 128) {                                \
            int r_ = i >> 3, c_ = (i & 7) << 3;                               \
            cpa16((dstu) + (r_ * 72 + c_) * 2, (srcp) + (size_t)r_ * HD + c_, 16); \
        }                                                                     \
        cpa_commit();                                                         \
    } while (0)

#define ISSUE_ER(bi) do {                                                     \
        int es_ = (bi) << 6;                                                  \
        for (int i = tid; i < 512; i += 128) {                                \
            int r_ = i >> 3, c_ = (i & 7) << 3;                               \
            int ar_ = base_abs + es_ + r_;                                    \
            cpa16(er_u + (r_ * 72 + c_) * 2, erp + (size_t)ar_ * HD + c_,     \
                  (ar_ < ER_L) ? 16 : 0);                                     \
        }                                                                     \
        cpa_commit();                                                         \
    } while (0)

#define R_MMA(bi) do {                                                        \
        int es_ = (bi) << 6;                                                  \
        _Pragma("unroll")                                                     \
        for (int nf = 0; nf < 8; nf++) {                                      \
            uint32_t bb[8];                                                   \
            ldsm4(bb,     er_u + ((nf * 8 + l8) * 72 + bg8) * 2);             \
            ldsm4(bb + 4, er_u + ((nf * 8 + l8) * 72 + 32 + bg8) * 2);        \
            float ca[4] = {0.f, 0.f, 0.f, 0.f};                               \
            float cb[4] = {0.f, 0.f, 0.f, 0.f};                               \
            mma16(ca, qa[0], bb);                                             \
            mma16(cb, qa[1], bb + 2);                                         \
            mma16(ca, qa[2], bb + 4);                                         \
            mma16(cb, qa[3], bb + 6);                                         \
            int j0 = (es_ + nf * 8 + 2 * t) & 127;                            \
            *(uint32_t*)&R_s[sA * 136 + j0] = pack_h2(ca[0] + cb[0], ca[1] + cb[1]); \
            *(uint32_t*)&R_s[sB * 136 + j0] = pack_h2(ca[2] + cb[2], ca[3] + cb[3]); \
        }                                                                     \
    } while (0)

    // q tile -> A fragments (staged via er_s)
    LOAD_TILE(er_u, qp);
    cpa_wait0();
    __syncthreads();
    uint32_t qa[4][4];
#pragma unroll
    for (int ks = 0; ks < 4; ks++)
        ldsm4(qa[ks], er_u + ((rs + ar) * 72 + ks * 16 + acol) * 2);
    __syncthreads();

    ISSUE_ER(0);
    cpa_wait0();
    __syncthreads();
    R_MMA(0);
    __syncthreads();
    ISSUE_ER(1);          // pending: ER1
    LOAD_TILE(k0_u, kp);  // pending: ER1, K0

    float m0 = -1e30f, m1 = -1e30f, sum0 = 0.f, sum1 = 0.f;

    for (int tt = 0; tt < 16; tt++) {
        const int t0 = tt << 6;
        const uint32_t kb_u = (tt & 1) ? k1_u : k0_u;

        cpa_wait1();      // ER(tt+1) landed
        __syncthreads();
        R_MMA(tt + 1);
        __syncthreads();
        if (tt < 15) {
            ISSUE_ER(tt + 2);
            LOAD_TILE((tt & 1) ? k0_u : k1_u, kp + (size_t)(t0 + 64) * HD);
            cpa_wait2();  // K(tt) landed
        } else {
            cpa_wait0();
        }
        __syncthreads();

        // scores (split accumulator chains)
        float sc[8][4];
#pragma unroll
        for (int nf = 0; nf < 8; nf++) {
            uint32_t bb[8];
            ldsm4(bb,     kb_u + ((nf * 8 + l8) * 72 + bg8) * 2);
            ldsm4(bb + 4, kb_u + ((nf * 8 + l8) * 72 + 32 + bg8) * 2);
            float ca[4] = {0.f, 0.f, 0.f, 0.f};
            float cb[4] = {0.f, 0.f, 0.f, 0.f};
            mma16(ca, qa[0], bb);
            mma16(cb, qa[1], bb + 2);
            mma16(ca, qa[2], bb + 4);
            mma16(cb, qa[3], bb + 6);
            int tp = nf * 8 + 2 * t;
            int cb2 = t0 + 63 + tp;
            sc[nf][0] = (ca[0] + cb[0] + __half2float(R_s[sA * 136 + ((cb2     - sA) & 127)])) * SCALE_L2;
            sc[nf][1] = (ca[1] + cb[1] + __half2float(R_s[sA * 136 + ((cb2 + 1 - sA) & 127)])) * SCALE_L2;
            sc[nf][2] = (ca[2] + cb[2] + __half2float(R_s[sB * 136 + ((cb2     - sB) & 127)])) * SCALE_L2;
            sc[nf][3] = (ca[3] + cb[3] + __half2float(R_s[sB * 136 + ((cb2 + 1 - sB) & 127)])) * SCALE_L2;
        }

        // tile max (quad reduce) -> running max
        float tm0 = -1e30f, tm1 = -1e30f;
#pragma unroll
        for (int nf = 0; nf < 8; nf++) {
            tm0 = fmaxf(tm0, fmaxf(sc[nf][0], sc[nf][1]));
            tm1 = fmaxf(tm1, fmaxf(sc[nf][2], sc[nf][3]));
        }
        tm0 = fmaxf(tm0, __shfl_xor_sync(0xffffffffu, tm0, 1));
        tm0 = fmaxf(tm0, __shfl_xor_sync(0xffffffffu, tm0, 2));
        tm1 = fmaxf(tm1, __shfl_xor_sync(0xffffffffu, tm1, 1));
        tm1 = fmaxf(tm1, __shfl_xor_sync(0xffffffffu, tm1, 2));
        float nm0 = fmaxf(m0, tm0), nm1 = fmaxf(m1, tm1);

        // p' = ex2(sc - nm), store fp16, accumulate sums
        float ts0 = 0.f, ts1 = 0.f;
#pragma unroll
        for (int nf = 0; nf < 8; nf++) {
            float p0 = ex2(sc[nf][0] - nm0), p1 = ex2(sc[nf][1] - nm0);
            float p2 = ex2(sc[nf][2] - nm1), p3 = ex2(sc[nf][3] - nm1);
            ts0 += p0 + p1;  ts1 += p2 + p3;
            int tp = nf * 8 + 2 * t;
            *(uint32_t*)&lgh_p[(size_t)sA * SEQ + t0 + tp] = pack_h2(p0, p1);
            *(uint32_t*)&lgh_p[(size_t)sB * SEQ + t0 + tp] = pack_h2(p2, p3);
        }
        ts0 += __shfl_xor_sync(0xffffffffu, ts0, 1);
        ts0 += __shfl_xor_sync(0xffffffffu, ts0, 2);
        ts1 += __shfl_xor_sync(0xffffffffu, ts1, 1);
        ts1 += __shfl_xor_sync(0xffffffffu, ts1, 2);
        sum0 = sum0 * ex2(m0 - nm0) + ts0;
        sum1 = sum1 * ex2(m1 - nm1) + ts1;
        m0 = nm0; m1 = nm1;
        if (t == 0) {
            mrun_p[(size_t)sA * 16 + tt] = nm0;
            mrun_p[(size_t)sB * 16 + tt] = nm1;
        }
    }

    if (t == 0) {
        stats[(size_t)bh * SEQ + s0 + sA] = make_float2(m0, 1.f / sum0);
        stats[(size_t)bh * SEQ + s0 + sB] = make_float2(m1, 1.f / sum1);
    }
#undef LOAD_TILE
#undef ISSUE_ER
#undef R_MMA
}

// ---------------------------------------------------------------------------
// Pass 2 (R14 proven config): attn = p' * cf, streamed fp16->fp32 with
// register prefetch; out = P @ V; V double-buffered; 4 blocks/SM, 128 regs.
// smem: v0|v1|p (9216 each) + st (512) + cf table (4096) = 32256 B.
// ---------------------------------------------------------------------------
__global__ void __launch_bounds__(128, 4) attn2_kernel(
    const __half* __restrict__ gv,
    float* __restrict__ out_f, float* __restrict__ attn_o,
    const __half* __restrict__ lgh_o, const float* __restrict__ mrun_o,
    const float2* __restrict__ stats)
{
    extern __shared__ char smem_c[];
    __half* v_s0 = (__half*)smem_c;              // [64][72]
    __half* v_s1 = (__half*)(smem_c + 9216);     // [64][72]
    __half* p_s  = (__half*)(smem_c + 18432);    // [64][72]
    float2* st_s = (float2*)(smem_c + 27648);    // [64]
    float*  cf_s = (float*)(smem_c + 28160);     // [64][16]

    const int tid  = threadIdx.x;
    const int warp = tid >> 5, lane = tid & 31;
    const int g = lane >> 2, t = lane & 3;
    const int rs = warp << 4;
    const int s0 = blockIdx.x << 6;
    const int bh = blockIdx.y;
    const int h  = bh & 15;

    const __half* vp = gv + (size_t)bh * SEQ * HD;
    float* attn_p = attn_o + ((size_t)bh * SEQ + s0) * SEQ;
    const __half* lgh_p = lgh_o + ((size_t)bh * SEQ + s0) * SEQ;

    const uint32_t v0_u = s2u(v_s0);
    const uint32_t v1_u = s2u(v_s1);
    const uint32_t p_u  = s2u(p_s);
    const int sA = rs + g, sB = rs + g + 8;

    const int ar   = (lane & 7) + ((lane >> 3) & 1) * 8;
    const int acol = (lane >> 4) * 8;
    const int l8   = lane & 7;
    const int bg8  = (lane >> 3) * 8;

    const int nrow = tid >> 4;
    const int ncol = (tid & 15) << 2;

#define LOAD_TILE(dstu, srcp) do {                                            \
        for (int i = tid; i < 512; i += 128) {                                \
            int r_ = i >> 3, c_ = (i & 7) << 3;                               \
            cpa16((dstu) + (r_ * 72 + c_) * 2, (srcp) + (size_t)r_ * HD + c_, 16); \
        }                                                                     \
        cpa_commit();                                                         \
    } while (0)

    // load stats + raw mrun, transform to cf = ex2(mrun - m_f) * inv
    if (tid < 64) st_s[tid] = stats[(size_t)bh * SEQ + s0 + tid];
    {
        const float* mrun_p = mrun_o + ((size_t)bh * SEQ + s0) * 16;
#pragma unroll
        for (int i = tid; i < 1024; i += 128) cf_s[i] = mrun_p[i];
    }
    __syncthreads();
#pragma unroll
    for (int i = tid; i < 1024; i += 128) {
        float2 st = st_s[i >> 4];
        cf_s[i] = ex2(cf_s[i] - st.x) * st.y;
    }

    float oacc[8][4];
#pragma unroll
    for (int ni = 0; ni < 8; ni++)
#pragma unroll
        for (int x = 0; x < 4; x++) oacc[ni][x] = 0.f;

    // prefetch p' tile 0 (fp16) + V(0)
    uint2 lg[8];
#pragma unroll
    for (int q8 = 0; q8 < 8; q8++)
        lg[q8] = *(const uint2*)&lgh_p[(size_t)(q8 * 8 + nrow) * SEQ + ncol];
    LOAD_TILE(v0_u, vp);
    __syncthreads();   // cf_s visible

    for (int tt = 0; tt < 16; tt++) {
        const int t0 = tt << 6;
        const uint32_t vb_u = (tt & 1) ? v1_u : v0_u;

        if (tt < 15)
            LOAD_TILE((tt & 1) ? v0_u : v1_u, vp + (size_t)(t0 + 64) * HD);

        // normalize tile tt: attn = p' * cf (float4 store), P = fp16 repack
#pragma unroll
        for (int q8 = 0; q8 < 8; q8++) {
            int r = q8 * 8 + nrow;
            float cf = cf_s[r * 16 + tt];
            __half2* hp = (__half2*)&lg[q8];
            float2 f0 = __half22float2(hp[0]);
            float2 f1 = __half22float2(hp[1]);
            float4 e = make_float4(f0.x * cf, f0.y * cf, f1.x * cf, f1.y * cf);
            *(float4*)&attn_p[(size_t)r * SEQ + t0 + ncol] = e;
            *(uint2*)&p_s[r * 72 + ncol] = make_uint2(pack_h2(e.x, e.y), pack_h2(e.z, e.w));
        }
        if (tt < 15) cpa_wait1(); else cpa_wait0();
        __syncthreads();

        if (tt < 15) {
#pragma unroll
            for (int q8 = 0; q8 < 8; q8++)
                lg[q8] = *(const uint2*)&lgh_p[(size_t)(q8 * 8 + nrow) * SEQ + t0 + 64 + ncol];
        }

        uint32_t pa[4][4];
#pragma unroll
        for (int ks = 0; ks < 4; ks++)
            ldsm4(pa[ks], p_u + ((rs + ar) * 72 + ks * 16 + acol) * 2);
#pragma unroll
        for (int ni = 0; ni < 8; ni++) {
            uint32_t bb[8];
            ldsm4t(bb,     vb_u + ((bg8 + l8) * 72 + ni * 8) * 2);
            ldsm4t(bb + 4, vb_u + ((32 + bg8 + l8) * 72 + ni * 8) * 2);
            mma16(oacc[ni], pa[0], bb);
            mma16(oacc[ni], pa[1], bb + 2);
            mma16(oacc[ni], pa[2], bb + 4);
            mma16(oacc[ni], pa[3], bb + 6);
        }
        __syncthreads();
    }

    const int b_i = bh >> 4;
    const int gsA = s0 + sA, gsB = s0 + sB;
#pragma unroll
    for (int ni = 0; ni < 8; ni++) {
        int col = h * HD + ni * 8 + 2 * t;
        *(float2*)(out_f + ((size_t)b_i * SEQ + gsA) * DM + col) = make_float2(oacc[ni][0], oacc[ni][1]);
        *(float2*)(out_f + ((size_t)b_i * SEQ + gsB) * DM + col) = make_float2(oacc[ni][2], oacc[ni][3]);
    }
#undef LOAD_TILE
}

// ---------------------------------------------------------------------------
extern "C" void kernel_launch(void* const* d_in, const int* in_sizes, int n_in,
                              void* d_out, int out_size)
{
    const float* query = (const float*)d_in[0];
    const float* key   = (const float*)d_in[1];
    const float* value = (const float*)d_in[2];
    const float* Wq = (const float*)d_in[3];
    const float* bq = (const float*)d_in[4];
    const float* Wk = (const float*)d_in[5];
    const float* bk = (const float*)d_in[6];
    const float* Wv = (const float*)d_in[7];
    const float* bv = (const float*)d_in[8];
    const float* Er = (const float*)d_in[9];
    float* outp = (float*)d_out;

    __half *ah, *wh, *gq, *gk, *gv, *ger, *glgh;
    float *gs, *gmr; float2 *gst;
    cudaGetSymbolAddress((void**)&ah,   g_ah);
    cudaGetSymbolAddress((void**)&wh,   g_wh);
    cudaGetSymbolAddress((void**)&gq,   g_q);
    cudaGetSymbolAddress((void**)&gk,   g_k);
    cudaGetSymbolAddress((void**)&gv,   g_v);
    cudaGetSymbolAddress((void**)&ger,  g_er);
    cudaGetSymbolAddress((void**)&glgh, g_lgh);
    cudaGetSymbolAddress((void**)&gmr,  g_mrun);
    cudaGetSymbolAddress((void**)&gs,   g_scratch);
    cudaGetSymbolAddress((void**)&gst,  g_stats);

    float* attn = (out_size > BS * SEQ * DM) ? (outp + (size_t)BS * SEQ * DM) : gs;

    cvt_all_kernel<<<17409, 256>>>(query, key, value, Wq, Wk, Wv, Er, ah, wh, ger);

    cudaFuncSetAttribute(proj_kernel, cudaFuncAttributeMaxDynamicSharedMemorySize, 73728);
    dim3 gp(DM / 128, (BS * SEQ) / 128, 3);
    proj_kernel<<<gp, 256, 73728>>>(ah, wh, bq, bk, bv, gq, gk, gv);

    cudaFuncSetAttribute(attn1_kernel, cudaFuncAttributeMaxDynamicSharedMemorySize, 45056);
    attn1_kernel<<<dim3(SEQ / 64, BS * NH), 128, 45056>>>(gq, gk, ger, glgh, gmr, gst);

    cudaFuncSetAttribute(attn2_kernel, cudaFuncAttributeMaxDynamicSharedMemorySize, 32256);
    attn2_kernel<<<dim3(SEQ / 64, BS * NH), 128, 32256>>>(gv, outp, attn, glgh, gmr, gst);
}